// round 4
// baseline (speedup 1.0000x reference)
#include <cuda_runtime.h>
#include <cstdint>
#include <cstddef>

// Problem dims
#define TT 700
#define BB 64
#define UU 400
#define GG 1600   // 4*U
#define FF 3
#define NCTA 148
#define NCOL 12   // 3 units * 4 gates per CTA (U padded to 148*3=444)

// ---------------- static device scratch (no runtime allocation allowed) ----
__device__ float g_xp [(size_t)TT * GG * BB];   // [t][col][b]  ~286.7 MB
__device__ float g_hs0[(size_t)TT * UU * BB];   // [t][u][b]    ~71.7 MB
__device__ float g_hs1[(size_t)TT * UU * BB];   // [t][u][b]
__device__ unsigned g_flags[NCTA];              // zero-init, monotonic barrier counters

// ---------------- helpers --------------------------------------------------
__device__ __forceinline__ unsigned ld_acq(const unsigned* p) {
    unsigned v;
    asm volatile("ld.acquire.gpu.u32 %0, [%1];" : "=r"(v) : "l"(p) : "memory");
    return v;
}
__device__ __forceinline__ void st_rel(unsigned* p, unsigned v) {
    asm volatile("st.release.gpu.u32 [%0], %1;" :: "l"(p), "r"(v) : "memory");
}
__device__ __forceinline__ float sigm(float x) { return 1.0f / (1.0f + __expf(-x)); }

// ---------------- layer-0 input projection (K = F = 3) ---------------------
// g_xp[t][col][b] = b0[col] + sum_d x[b][t][d] * Wx0[d][col]
__global__ void xp_l0_kernel(const float* __restrict__ x,
                             const float* __restrict__ Wx0,
                             const float* __restrict__ b0)
{
    int t = blockIdx.x;
    __shared__ float xs[BB * FF];
    __shared__ float ws[FF * GG];
    __shared__ float bs[GG];
    int tid = threadIdx.x;
    if (tid < BB * FF) {
        int b = tid / FF, d = tid % FF;
        xs[tid] = x[(size_t)b * (TT * FF) + t * FF + d];
    }
    for (int i = tid; i < FF * GG; i += 256) ws[i] = Wx0[i];
    for (int i = tid; i < GG; i += 256) bs[i] = b0[i];
    __syncthreads();
    float* dst = g_xp + (size_t)t * GG * BB;
    for (int idx = tid; idx < GG * BB; idx += 256) {
        int col = idx >> 6, b = idx & 63;
        float v = bs[col]
                + xs[b * 3 + 0] * ws[col]
                + xs[b * 3 + 1] * ws[GG + col]
                + xs[b * 3 + 2] * ws[2 * GG + col];
        dst[idx] = v;
    }
}

// ---------------- xp GEMM for layers 1,2 (K = U = 400) ----------------------
// g_xp[t][col][b] = bias[col] + sum_u hs[t][u][b] * Wx[u][col]
// grid (25, 700), block 256; CTA tile = 64 cols x 64 b, K-chunks of 16.
__global__ void __launch_bounds__(256) xp_gemm_kernel(int srcsel,
                                                      const float* __restrict__ Wx,
                                                      const float* __restrict__ bias)
{
    const float* hs = srcsel ? g_hs1 : g_hs0;
    int t  = blockIdx.y;
    int c0 = blockIdx.x * 64;

    __shared__ float4 As4[16 * 16];  // [k16][b64]
    __shared__ float4 Ws4[16 * 16];  // [k16][c64]

    int tid = threadIdx.x;
    int tc = tid & 15;   // col group (4 cols)
    int tb = tid >> 4;   // b group (4 b)
    int r  = tid >> 4;   // load row
    int q  = tid & 15;   // load chunk

    float acc[4][4];
#pragma unroll
    for (int c = 0; c < 4; c++)
#pragma unroll
        for (int b = 0; b < 4; b++) acc[c][b] = 0.0f;

    const float* hsrc = hs + (size_t)t * UU * BB;

    for (int kc = 0; kc < UU; kc += 16) {
        As4[tid] = ((const float4*)(hsrc + (size_t)(kc + r) * BB))[q];
        Ws4[tid] = ((const float4*)(Wx + (size_t)(kc + r) * GG + c0))[q];
        __syncthreads();
#pragma unroll
        for (int k = 0; k < 16; k++) {
            float4 a4 = As4[k * 16 + tb];
            float4 w4 = Ws4[k * 16 + tc];
            acc[0][0] += w4.x * a4.x; acc[0][1] += w4.x * a4.y;
            acc[0][2] += w4.x * a4.z; acc[0][3] += w4.x * a4.w;
            acc[1][0] += w4.y * a4.x; acc[1][1] += w4.y * a4.y;
            acc[1][2] += w4.y * a4.z; acc[1][3] += w4.y * a4.w;
            acc[2][0] += w4.z * a4.x; acc[2][1] += w4.z * a4.y;
            acc[2][2] += w4.z * a4.z; acc[2][3] += w4.z * a4.w;
            acc[3][0] += w4.w * a4.x; acc[3][1] += w4.w * a4.y;
            acc[3][2] += w4.w * a4.z; acc[3][3] += w4.w * a4.w;
        }
        __syncthreads();
    }

#pragma unroll
    for (int c = 0; c < 4; c++) {
        int col = c0 + tc * 4 + c;
        float bv = bias[col];
        float4 o;
        o.x = acc[c][0] + bv; o.y = acc[c][1] + bv;
        o.z = acc[c][2] + bv; o.w = acc[c][3] + bv;
        ((float4*)(g_xp + (size_t)(t * GG + col) * BB))[tb] = o;
    }
}

// ---------------- persistent per-layer LSTM scan ----------------------------
// 148 CTAs x 256 threads, all co-resident (<=1 CTA/SM via 135 KB dyn smem).
// CTA owns units u0..u0+2 (u >= 400 are zero-weight fakes). Per step:
//   z[b, col] = xp[t][col][b] + sum_k h_sm[k][b] * w_sm[k][col]
// thread (kk, colg, rowg): 4 rows x 3 cols x 100-k partial; smem reduce; gates.
__global__ void __launch_bounds__(256, 1) scan_kernel(const float* __restrict__ Wh_l,
                                                      const float* __restrict__ pi_l,
                                                      const float* __restrict__ pf_l,
                                                      const float* __restrict__ po_l,
                                                      int outsel)
{
    float* hs_out = outsel ? g_hs1 : g_hs0;

    extern __shared__ float sm[];
    float* h_sm = sm;                        // [400][64]
    float* w_sm = sm + UU * BB;              // [400][12]
    float* red  = w_sm + UU * NCOL;          // [4][12][64]
    float* c_sm = red + 4 * NCOL * BB;       // [3][64]

    int tid = threadIdx.x;
    int cta = blockIdx.x;
    int u0  = cta * 3;

    // init smem
    for (int i = tid; i < UU * BB; i += 256) h_sm[i] = 0.0f;
    for (int i = tid; i < UU * NCOL; i += 256) {
        int k = i / NCOL, lc = i % NCOL;
        int j = lc >> 2, g = lc & 3;
        int u = u0 + j;
        w_sm[i] = (u < UU) ? Wh_l[(size_t)k * GG + g * UU + u] : 0.0f;
    }
    if (tid < 3 * BB) c_sm[tid] = 0.0f;

    // gate-thread constants
    float piv = 0.f, pfv = 0.f, pov = 0.f;
    int gj = 0, gb = 0, gu = 0;
    bool gthr = (tid < 3 * BB), gvalid = false;
    if (gthr) {
        gj = tid >> 6; gb = tid & 63; gu = u0 + gj;
        gvalid = (gu < UU);
        if (gvalid) { piv = pi_l[gu]; pfv = pf_l[gu]; pov = po_l[gu]; }
    }

    unsigned base = g_flags[cta];  // all CTAs see identical value (stream-ordered)

    // z-phase thread mapping
    int kk   = tid >> 6;         // 0..3  (k quarter)
    int colg = (tid >> 4) & 3;   // 0..3  (3 local cols each)
    int rowg = tid & 15;         // 0..15 (4 b-rows each)
    const float* wbase = w_sm + (kk * 100) * NCOL + colg * 3;
    const float* hbase = h_sm + (kk * 100) * BB + rowg * 4;
    float* redp = red + (size_t)(kk * NCOL + colg * 3) * BB + rowg * 4;

    __syncthreads();

    for (int t = 0; t < TT; t++) {
        // prefetch xp for the gate phase (hidden under the k-loop)
        float xpv0 = 0.f, xpv1 = 0.f, xpv2 = 0.f, xpv3 = 0.f;
        if (gvalid) {
            const float* xpp = g_xp + ((size_t)t * GG + gu) * BB + gb;
            xpv0 = __ldg(xpp);
            xpv1 = __ldg(xpp + (size_t)UU * BB);
            xpv2 = __ldg(xpp + (size_t)2 * UU * BB);
            xpv3 = __ldg(xpp + (size_t)3 * UU * BB);
        }

        float acc[3][4];
#pragma unroll
        for (int c = 0; c < 3; c++)
#pragma unroll
            for (int rr = 0; rr < 4; rr++) acc[c][rr] = 0.0f;

        {
            const float* hp = hbase;
            const float* wp = wbase;
#pragma unroll 4
            for (int k = 0; k < 100; k++) {
                float4 h4 = *(const float4*)hp;
                float w0 = wp[0], w1 = wp[1], w2 = wp[2];
                acc[0][0] += h4.x * w0; acc[0][1] += h4.y * w0;
                acc[0][2] += h4.z * w0; acc[0][3] += h4.w * w0;
                acc[1][0] += h4.x * w1; acc[1][1] += h4.y * w1;
                acc[1][2] += h4.z * w1; acc[1][3] += h4.w * w1;
                acc[2][0] += h4.x * w2; acc[2][1] += h4.y * w2;
                acc[2][2] += h4.z * w2; acc[2][3] += h4.w * w2;
                hp += BB; wp += NCOL;
            }
        }
#pragma unroll
        for (int c = 0; c < 3; c++)
            *(float4*)(redp + (size_t)c * BB) =
                make_float4(acc[c][0], acc[c][1], acc[c][2], acc[c][3]);
        __syncthreads();

        // gate phase (192 threads: one per (unit j, batch b))
        if (gthr) {
            float s0 = 0.f, s1 = 0.f, s2 = 0.f, s3 = 0.f;
#pragma unroll
            for (int qy = 0; qy < 4; qy++) {
                const float* rp = red + (size_t)(qy * NCOL + gj * 4) * BB + gb;
                s0 += rp[0]; s1 += rp[BB]; s2 += rp[2 * BB]; s3 += rp[3 * BB];
            }
            float z0 = xpv0 + s0, z1 = xpv1 + s1, z2 = xpv2 + s2, z3 = xpv3 + s3;
            float cold = c_sm[tid];
            float iv = sigm(z0 + piv * cold);
            float fv = sigm(z1 + pfv * cold);
            float cn = fv * cold + iv * tanhf(z2);
            float ov = sigm(z3 + pov * cn);
            float hv = ov * tanhf(cn);
            c_sm[tid] = cn;
            if (gvalid)
                hs_out[((size_t)t * UU + gu) * BB + gb] = hv;
            __threadfence();
        }
        __syncthreads();

        if (t < TT - 1) {
            // grid barrier: per-CTA monotonic flag + warp-0 poll of all 148 flags
            unsigned tgt = base + (unsigned)t + 1u;
            if (tid == 0) st_rel(&g_flags[cta], tgt);
            if (tid < 32) {
                for (;;) {
                    bool ok = true;
                    for (int i = tid; i < NCTA; i += 32)
                        if (ld_acq(&g_flags[i]) < tgt) ok = false;
                    if (__all_sync(0xffffffffu, ok)) break;
                    __nanosleep(100);
                }
            }
            __syncthreads();
            // refill h_sm with h_t (everyone's writes now visible)
            const float4* src = (const float4*)(hs_out + (size_t)t * UU * BB);
            float4* dst = (float4*)h_sm;
            for (int i = tid; i < UU * BB / 4; i += 256) dst[i] = src[i];
            __syncthreads();
        }
    }
}

// ---------------- final projection ------------------------------------------
// out[b][t][f] = bd[f] + sum_u hs0[t][u][b] * Wd[u][f]
__global__ void final_kernel(const float* __restrict__ Wd,
                             const float* __restrict__ bd,
                             float* __restrict__ out)
{
    int t = blockIdx.x;
    int tid = threadIdx.x;  // 192
    __shared__ float wds[UU * FF];
    for (int i = tid; i < UU * FF; i += 192) wds[i] = Wd[i];
    __syncthreads();
    int b = tid / FF, f = tid % FF;
    const float* h = g_hs0 + (size_t)t * UU * BB;
    float acc = bd[f];
#pragma unroll 4
    for (int u = 0; u < UU; u++)
        acc += h[(size_t)u * BB + b] * wds[u * FF + f];
    out[(size_t)b * (TT * FF) + t * FF + f] = acc;
}

// ---------------- launch -----------------------------------------------------
extern "C" void kernel_launch(void* const* d_in, const int* in_sizes, int n_in,
                              void* d_out, int out_size)
{
    (void)in_sizes; (void)n_in; (void)out_size;
    const float* x   = (const float*)d_in[0];
    const float* Wx0 = (const float*)d_in[1];
    const float* Wx1 = (const float*)d_in[2];
    const float* Wx2 = (const float*)d_in[3];
    const float* Wh  = (const float*)d_in[4];
    const float* bb  = (const float*)d_in[5];
    const float* pi  = (const float*)d_in[6];
    const float* pf  = (const float*)d_in[7];
    const float* po  = (const float*)d_in[8];
    const float* Wd  = (const float*)d_in[9];
    const float* bd  = (const float*)d_in[10];
    float* out = (float*)d_out;

    const int SMEM_BYTES = (UU * BB + UU * NCOL + 4 * NCOL * BB + 3 * BB) * 4; // 134,656 B
    cudaFuncSetAttribute(scan_kernel, cudaFuncAttributeMaxDynamicSharedMemorySize, SMEM_BYTES);

    // layer 0
    xp_l0_kernel<<<TT, 256>>>(x, Wx0, bb);
    scan_kernel<<<NCTA, 256, SMEM_BYTES>>>(Wh, pi, pf, po, /*outsel=*/0);
    // layer 1
    xp_gemm_kernel<<<dim3(GG / 64, TT), 256>>>(/*src=*/0, Wx1, bb + GG);
    scan_kernel<<<NCTA, 256, SMEM_BYTES>>>(Wh + (size_t)UU * GG, pi + UU, pf + UU, po + UU, 1);
    // layer 2
    xp_gemm_kernel<<<dim3(GG / 64, TT), 256>>>(/*src=*/1, Wx2, bb + 2 * GG);
    scan_kernel<<<NCTA, 256, SMEM_BYTES>>>(Wh + (size_t)2 * UU * GG, pi + 2 * UU, pf + 2 * UU, po + 2 * UU, 0);
    // output projection
    final_kernel<<<TT, 192>>>(Wd, bd, out);
}